// round 3
// baseline (speedup 1.0000x reference)
#include <cuda_runtime.h>

// UniSAGE is fully linear => pull the final averaging functionals backwards.
// Only scalar/float2 per-vertex & per-edge vectors are materialized.
// R3: single-wave occupancy for NNZ passes (3 elems/thread, strided),
// memsetAsync zeroing instead of a zero kernel.

#define NV   100000
#define NE   200000
#define NNZt 800000
#define DIN  14
#define HID  128
#define WP   (1.0f / (float)NV)
#define WR   (1.0f / (float)NE)

// NNZ-pass geometry: one ~full wave, 3 elements per thread, strided.
#define NNZ_BLK  256
#define NNZ_GRID 1042                       // 1042*256 = 266752 threads
#define NNZ_STRIDE (NNZ_BLK * NNZ_GRID)     // 266752; 3*266752 >= 800000

// -------- device scratch (allocation-free) --------
__device__ float  g_deg[NV];
__device__ float2 g_pv2[NV];    // {p_raw, r2_raw}
__device__ float  g_q  [NV];    // (p_raw + 1/NV) / deg
__device__ float  g_p2 [NV];    // p2_raw
__device__ float2 g_ze [NE];    // {zp, edeg}
__device__ float  g_zp2[NE];
__device__ float  g_acc[32];    // [0..13]=p2^T X, [14..27]=r2^T X, 28=Σp, 29=Σp2, 30=Σr2

__device__ __forceinline__ void red2(float2* a, float x, float y) {
    asm volatile("red.global.add.v2.f32 [%0], {%1,%2};" :: "l"(a), "f"(x), "f"(y) : "memory");
}
__device__ __forceinline__ void red1(float* a, float x) {
    asm volatile("red.global.add.f32 [%0], %1;" :: "l"(a), "f"(x) : "memory");
}

__global__ void __launch_bounds__(NNZ_BLK) k_deg(const int* __restrict__ rows) {
    int t = blockIdx.x * NNZ_BLK + threadIdx.x;
#pragma unroll
    for (int k = 0; k < 3; k++) {
        int i = t + k * NNZ_STRIDE;
        if (i < NNZt) red1(&g_deg[rows[i]], 1.f);
    }
}

// ze[e] += { (1/NV)/deg[v], 1 }   (zp scatter + edge-degree count fused)
__global__ void __launch_bounds__(NNZ_BLK) k_scat1(const int* __restrict__ rows,
                                                   const int* __restrict__ cols) {
    int t = blockIdx.x * NNZ_BLK + threadIdx.x;
#pragma unroll
    for (int k = 0; k < 3; k++) {
        int i = t + k * NNZ_STRIDE;
        if (i < NNZt) {
            float d = g_deg[rows[i]];
            red2(&g_ze[cols[i]], __fdividef(WP, d), 1.f);
        }
    }
}

// pv2[v] += { zp[e], edeg[e]/NE }
__global__ void __launch_bounds__(NNZ_BLK) k_gath1(const int* __restrict__ rows,
                                                   const int* __restrict__ cols) {
    int t = blockIdx.x * NNZ_BLK + threadIdx.x;
#pragma unroll
    for (int k = 0; k < 3; k++) {
        int i = t + k * NNZ_STRIDE;
        if (i < NNZt) {
            float2 z = g_ze[cols[i]];
            red2(&g_pv2[rows[i]], z.x, z.y * WR);
        }
    }
}

// q[v] = (p_raw[v] + 1/NV) / deg[v]
__global__ void k_prep() {
    int v = blockIdx.x * blockDim.x + threadIdx.x;
    if (v < NV) {
        float d = g_deg[v];
        g_q[v] = __fdividef(g_pv2[v].x + WP, d > 0.f ? d : 1.f);
    }
}

__global__ void __launch_bounds__(NNZ_BLK) k_scat2(const int* __restrict__ rows,
                                                   const int* __restrict__ cols) {
    int t = blockIdx.x * NNZ_BLK + threadIdx.x;
#pragma unroll
    for (int k = 0; k < 3; k++) {
        int i = t + k * NNZ_STRIDE;
        if (i < NNZt) red1(&g_zp2[cols[i]], g_q[rows[i]]);
    }
}

__global__ void __launch_bounds__(NNZ_BLK) k_gath2(const int* __restrict__ rows,
                                                   const int* __restrict__ cols) {
    int t = blockIdx.x * NNZ_BLK + threadIdx.x;
#pragma unroll
    for (int k = 0; k < 3; k++) {
        int i = t + k * NNZ_STRIDE;
        if (i < NNZt) red1(&g_p2[rows[i]], g_zp2[cols[i]]);
    }
}

// per-vertex reduction: Σp, Σp2, Σr2, p2^T X, r2^T X
__global__ void k_reduce(const float* __restrict__ x0) {
    int v = blockIdx.x * blockDim.x + threadIdx.x;
    float vals[31];
#pragma unroll
    for (int k = 0; k < 31; k++) vals[k] = 0.f;
    if (v < NV) {
        float2 pr = g_pv2[v];
        float pv  = pr.x + WP;                    // full p (identity folded)
        float p2v = g_p2[v] + pv;                 // p2 = p2_raw + p
        float r2v = pr.y + g_deg[v] * WR;         // r2 = r2_raw + r
        const float* xr = x0 + (long long)v * DIN;
#pragma unroll
        for (int j = 0; j < DIN; j++) {
            float x = xr[j];
            vals[j]      = p2v * x;
            vals[14 + j] = r2v * x;
        }
        vals[28] = pv; vals[29] = p2v; vals[30] = r2v;
    }
#pragma unroll
    for (int k = 0; k < 31; k++) {
#pragma unroll
        for (int off = 16; off > 0; off >>= 1)
            vals[k] += __shfl_down_sync(0xffffffffu, vals[k], off);
    }
    __shared__ float sh[8 * 31];
    int warp = threadIdx.x >> 5, lane = threadIdx.x & 31;
    if (lane == 0) {
#pragma unroll
        for (int k = 0; k < 31; k++) sh[warp * 31 + k] = vals[k];
    }
    __syncthreads();
    if (threadIdx.x < 31) {
        float s = 0.f;
#pragma unroll
        for (int w = 0; w < 8; w++) s += sh[w * 31 + threadIdx.x];
        atomicAdd(&g_acc[threadIdx.x], s);
    }
}

// tiny GEMV chain: (1x14) -> (1x128) -> (1x128) -> (1x128) -> scalar, both branches
__global__ void k_final(const float* __restrict__ W0, const float* __restrict__ b0,
                        const float* __restrict__ Wl0, const float* __restrict__ bl0,
                        const float* __restrict__ Wl1, const float* __restrict__ bl1,
                        const float* __restrict__ Wo0, const float* __restrict__ bo0,
                        const float* __restrict__ Wo1, const float* __restrict__ bo1,
                        float* __restrict__ out) {
    __shared__ float a0[HID], c0[HID], a1[HID], c1[HID], red[HID];
    int h = threadIdx.x;
    float sp  = g_acc[28];
    float sp2 = g_acc[29];
    float sr2 = g_acc[30];
    float sr  = (float)NNZt / (float)NE;

    float sa = 0.f, sc = 0.f;
#pragma unroll
    for (int j = 0; j < DIN; j++) {
        float w = W0[j * HID + h];
        sa += g_acc[j] * w;
        sc += g_acc[14 + j] * w;
    }
    a0[h] = sa + sp2 * b0[h];
    c0[h] = sc + sr2 * b0[h];
    __syncthreads();

    sa = 0.f; sc = 0.f;
    for (int m = 0; m < HID; m++) {
        float w = Wl0[m * HID + h];
        sa += a0[m] * w;
        sc += c0[m] * w;
    }
    a1[h] = sa + sp2 * bl0[h];
    c1[h] = sc + sr2 * bl0[h];
    __syncthreads();

    sa = 0.f; sc = 0.f;
    for (int m = 0; m < HID; m++) {
        float w = Wl1[m * HID + h];
        sa += a1[m] * w;
        sc += c1[m] * w;
    }
    float a2h = sa + sp * bl1[h];   // p^T h2
    float c2h = sc + sr * bl1[h];   // r^T h2
    red[h] = a2h * Wo0[h] + c2h * Wo1[h];
    __syncthreads();

    for (int s = HID / 2; s > 0; s >>= 1) {
        if (h < s) red[h] += red[h + s];
        __syncthreads();
    }
    if (h == 0) out[0] = red[0] + bo0[0] + bo1[0];
}

extern "C" void kernel_launch(void* const* d_in, const int* in_sizes, int n_in,
                              void* d_out, int out_size) {
    const float* x_0  = (const float*)d_in[0];
    const int*   rows = (const int*)d_in[2];
    const int*   cols = (const int*)d_in[3];
    const float* W0   = (const float*)d_in[4];
    const float* b0   = (const float*)d_in[5];
    const float* Wl0  = (const float*)d_in[8];
    const float* bl0  = (const float*)d_in[9];
    const float* Wl1  = (const float*)d_in[10];
    const float* bl1  = (const float*)d_in[11];
    const float* Wo0  = (const float*)d_in[12];
    const float* bo0  = (const float*)d_in[13];
    const float* Wo1  = (const float*)d_in[14];
    const float* bo1  = (const float*)d_in[15];
    float* out = (float*)d_out;

    // zero scratch via memset nodes (graph-capturable, no allocation)
    void *p_deg, *p_pv2, *p_q, *p_p2, *p_ze, *p_zp2, *p_acc;
    cudaGetSymbolAddress(&p_deg, g_deg);
    cudaGetSymbolAddress(&p_pv2, g_pv2);
    cudaGetSymbolAddress(&p_q,   g_q);
    cudaGetSymbolAddress(&p_p2,  g_p2);
    cudaGetSymbolAddress(&p_ze,  g_ze);
    cudaGetSymbolAddress(&p_zp2, g_zp2);
    cudaGetSymbolAddress(&p_acc, g_acc);
    cudaMemsetAsync(p_deg, 0, NV * sizeof(float));
    cudaMemsetAsync(p_pv2, 0, NV * sizeof(float2));
    cudaMemsetAsync(p_p2,  0, NV * sizeof(float));
    cudaMemsetAsync(p_ze,  0, NE * sizeof(float2));
    cudaMemsetAsync(p_zp2, 0, NE * sizeof(float));
    cudaMemsetAsync(p_acc, 0, 32 * sizeof(float));

    const int T = 256;
    const int gNV = (NV + T - 1) / T;

    k_deg  <<<NNZ_GRID, NNZ_BLK>>>(rows);
    k_scat1<<<NNZ_GRID, NNZ_BLK>>>(rows, cols);
    k_gath1<<<NNZ_GRID, NNZ_BLK>>>(rows, cols);
    k_prep <<<gNV, T>>>();
    k_scat2<<<NNZ_GRID, NNZ_BLK>>>(rows, cols);
    k_gath2<<<NNZ_GRID, NNZ_BLK>>>(rows, cols);
    k_reduce<<<gNV, T>>>(x_0);
    k_final<<<1, HID>>>(W0, b0, Wl0, bl0, Wl1, bl1, Wo0, bo0, Wo1, bo1, out);
}

// round 4
// speedup vs baseline: 1.1278x; 1.1278x over previous
#include <cuda_runtime.h>

// UniSAGE is fully linear => pull the final averaging functionals backwards.
// Only scalar/float2 per-vertex & per-edge vectors are materialized.
// R4: revert NNZ passes to proven R2 int4 form (LSU-issue bound, near floor);
// single contiguous memset node; fuse final GEMV into reduce via ticket.

#define NV   100000
#define NE   200000
#define NNZt 800000
#define DIN  14
#define HID  128
#define WP   (1.0f / (float)NV)
#define WR   (1.0f / (float)NE)

// -------- device scratch (allocation-free), one block for a single memset ----
struct Scratch {
    float  deg[NV];
    float2 pv2[NV];    // {p_raw, r2_raw}
    float  p2 [NV];    // p2_raw
    float2 ze [NE];    // {zp, edeg}
    float  zp2[NE];
    float  acc[32];    // [0..13]=p2^T X, [14..27]=r2^T X, 28=Σp, 29=Σp2, 30=Σr2
    unsigned int tick;
};
__device__ Scratch g_s;
__device__ float g_q[NV];      // (p_raw + 1/NV)/deg  (written before read; no zeroing)

__device__ __forceinline__ void red2(float2* a, float x, float y) {
    asm volatile("red.global.add.v2.f32 [%0], {%1,%2};" :: "l"(a), "f"(x), "f"(y) : "memory");
}
__device__ __forceinline__ void red1(float* a, float x) {
    asm volatile("red.global.add.f32 [%0], %1;" :: "l"(a), "f"(x) : "memory");
}

__global__ void k_deg(const int* __restrict__ rows) {
    int i = blockIdx.x * blockDim.x + threadIdx.x;
    if (i * 4 < NNZt) {
        int4 r = ((const int4*)rows)[i];
        red1(&g_s.deg[r.x], 1.f);
        red1(&g_s.deg[r.y], 1.f);
        red1(&g_s.deg[r.z], 1.f);
        red1(&g_s.deg[r.w], 1.f);
    }
}

// ze[e] += { (1/NV)/deg[v], 1 }   (zp scatter + edge-degree count fused)
__global__ void k_scat1(const int* __restrict__ rows, const int* __restrict__ cols) {
    int i = blockIdx.x * blockDim.x + threadIdx.x;
    if (i * 4 < NNZt) {
        int4 r = ((const int4*)rows)[i];
        int4 c = ((const int4*)cols)[i];
        float dx = g_s.deg[r.x], dy = g_s.deg[r.y], dz = g_s.deg[r.z], dw = g_s.deg[r.w];
        red2(&g_s.ze[c.x], __fdividef(WP, dx), 1.f);
        red2(&g_s.ze[c.y], __fdividef(WP, dy), 1.f);
        red2(&g_s.ze[c.z], __fdividef(WP, dz), 1.f);
        red2(&g_s.ze[c.w], __fdividef(WP, dw), 1.f);
    }
}

// pv2[v] += { zp[e], edeg[e]/NE }
__global__ void k_gath1(const int* __restrict__ rows, const int* __restrict__ cols) {
    int i = blockIdx.x * blockDim.x + threadIdx.x;
    if (i * 4 < NNZt) {
        int4 r = ((const int4*)rows)[i];
        int4 c = ((const int4*)cols)[i];
        float2 zx = g_s.ze[c.x], zy = g_s.ze[c.y], zz = g_s.ze[c.z], zw = g_s.ze[c.w];
        red2(&g_s.pv2[r.x], zx.x, zx.y * WR);
        red2(&g_s.pv2[r.y], zy.x, zy.y * WR);
        red2(&g_s.pv2[r.z], zz.x, zz.y * WR);
        red2(&g_s.pv2[r.w], zw.x, zw.y * WR);
    }
}

// q[v] = (p_raw[v] + 1/NV) / deg[v]
__global__ void k_prep() {
    int v = blockIdx.x * blockDim.x + threadIdx.x;
    if (v < NV) {
        float d = g_s.deg[v];
        g_q[v] = __fdividef(g_s.pv2[v].x + WP, d > 0.f ? d : 1.f);
    }
}

__global__ void k_scat2(const int* __restrict__ rows, const int* __restrict__ cols) {
    int i = blockIdx.x * blockDim.x + threadIdx.x;
    if (i * 4 < NNZt) {
        int4 r = ((const int4*)rows)[i];
        int4 c = ((const int4*)cols)[i];
        red1(&g_s.zp2[c.x], g_q[r.x]);
        red1(&g_s.zp2[c.y], g_q[r.y]);
        red1(&g_s.zp2[c.z], g_q[r.z]);
        red1(&g_s.zp2[c.w], g_q[r.w]);
    }
}

__global__ void k_gath2(const int* __restrict__ rows, const int* __restrict__ cols) {
    int i = blockIdx.x * blockDim.x + threadIdx.x;
    if (i * 4 < NNZt) {
        int4 r = ((const int4*)rows)[i];
        int4 c = ((const int4*)cols)[i];
        red1(&g_s.p2[r.x], g_s.zp2[c.x]);
        red1(&g_s.p2[r.y], g_s.zp2[c.y]);
        red1(&g_s.p2[r.z], g_s.zp2[c.z]);
        red1(&g_s.p2[r.w], g_s.zp2[c.w]);
    }
}

// per-vertex reduction (Σp, Σp2, Σr2, p2^T X, r2^T X) + fused final GEMV chain
// in the last-finishing block (ticket pattern).
__global__ void k_reduce_final(const float* __restrict__ x0,
                               const float* __restrict__ W0, const float* __restrict__ b0,
                               const float* __restrict__ Wl0, const float* __restrict__ bl0,
                               const float* __restrict__ Wl1, const float* __restrict__ bl1,
                               const float* __restrict__ Wo0, const float* __restrict__ bo0,
                               const float* __restrict__ Wo1, const float* __restrict__ bo1,
                               float* __restrict__ out) {
    int v = blockIdx.x * blockDim.x + threadIdx.x;
    float vals[31];
#pragma unroll
    for (int k = 0; k < 31; k++) vals[k] = 0.f;
    if (v < NV) {
        float2 pr = g_s.pv2[v];
        float pv  = pr.x + WP;                    // full p (identity folded)
        float p2v = g_s.p2[v] + pv;               // p2 = p2_raw + p
        float r2v = pr.y + g_s.deg[v] * WR;       // r2 = r2_raw + r
        const float* xr = x0 + (long long)v * DIN;
#pragma unroll
        for (int j = 0; j < DIN; j++) {
            float x = xr[j];
            vals[j]      = p2v * x;
            vals[14 + j] = r2v * x;
        }
        vals[28] = pv; vals[29] = p2v; vals[30] = r2v;
    }
#pragma unroll
    for (int k = 0; k < 31; k++) {
#pragma unroll
        for (int off = 16; off > 0; off >>= 1)
            vals[k] += __shfl_down_sync(0xffffffffu, vals[k], off);
    }
    __shared__ float sh[8 * 31];
    int warp = threadIdx.x >> 5, lane = threadIdx.x & 31;
    if (lane == 0) {
#pragma unroll
        for (int k = 0; k < 31; k++) sh[warp * 31 + k] = vals[k];
    }
    __syncthreads();
    if (threadIdx.x < 31) {
        float s = 0.f;
#pragma unroll
        for (int w = 0; w < 8; w++) s += sh[w * 31 + threadIdx.x];
        atomicAdd(&g_s.acc[threadIdx.x], s);
    }

    // ---- ticket: last block to finish runs the tiny GEMV chain ----
    __threadfence();
    __shared__ unsigned int is_last;
    if (threadIdx.x == 0)
        is_last = (atomicInc(&g_s.tick, gridDim.x - 1) == gridDim.x - 1) ? 1u : 0u;
    __syncthreads();
    if (!is_last) return;
    __threadfence();   // acquire side: see all g_s.acc atomics

    __shared__ float a0[HID], c0[HID], a1[HID], c1[HID], red[HID];
    int h = threadIdx.x;      // blockDim = 256; threads >= HID participate in syncs only
    float sp  = g_s.acc[28];
    float sp2 = g_s.acc[29];
    float sr2 = g_s.acc[30];
    float sr  = (float)NNZt / (float)NE;   // 1^T (deg/NE) exactly

    if (h < HID) {
        float sa = 0.f, sc = 0.f;
#pragma unroll
        for (int j = 0; j < DIN; j++) {
            float w = W0[j * HID + h];
            sa += g_s.acc[j] * w;
            sc += g_s.acc[14 + j] * w;
        }
        a0[h] = sa + sp2 * b0[h];
        c0[h] = sc + sr2 * b0[h];
    }
    __syncthreads();
    if (h < HID) {
        float sa = 0.f, sc = 0.f;
        for (int m = 0; m < HID; m++) {
            float w = Wl0[m * HID + h];
            sa += a0[m] * w;
            sc += c0[m] * w;
        }
        a1[h] = sa + sp2 * bl0[h];
        c1[h] = sc + sr2 * bl0[h];
    }
    __syncthreads();
    if (h < HID) {
        float sa = 0.f, sc = 0.f;
        for (int m = 0; m < HID; m++) {
            float w = Wl1[m * HID + h];
            sa += a1[m] * w;
            sc += c1[m] * w;
        }
        float a2h = sa + sp * bl1[h];   // p^T h2
        float c2h = sc + sr * bl1[h];   // r^T h2
        red[h] = a2h * Wo0[h] + c2h * Wo1[h];
    }
    __syncthreads();
    for (int s = HID / 2; s > 0; s >>= 1) {
        if (h < s) red[h] += red[h + s];
        __syncthreads();
    }
    if (h == 0) out[0] = red[0] + bo0[0] + bo1[0];
}

extern "C" void kernel_launch(void* const* d_in, const int* in_sizes, int n_in,
                              void* d_out, int out_size) {
    const float* x_0  = (const float*)d_in[0];
    const int*   rows = (const int*)d_in[2];
    const int*   cols = (const int*)d_in[3];
    const float* W0   = (const float*)d_in[4];
    const float* b0   = (const float*)d_in[5];
    const float* Wl0  = (const float*)d_in[8];
    const float* bl0  = (const float*)d_in[9];
    const float* Wl1  = (const float*)d_in[10];
    const float* bl1  = (const float*)d_in[11];
    const float* Wo0  = (const float*)d_in[12];
    const float* bo0  = (const float*)d_in[13];
    const float* Wo1  = (const float*)d_in[14];
    const float* bo1  = (const float*)d_in[15];
    float* out = (float*)d_out;

    // zero all scratch with ONE memset node (graph-capturable, no allocation)
    void* p_s;
    cudaGetSymbolAddress(&p_s, g_s);
    cudaMemsetAsync(p_s, 0, sizeof(Scratch));

    const int T = 256;
    const int gNnz4 = (NNZt / 4 + T - 1) / T;   // 782
    const int gNV   = (NV + T - 1) / T;         // 391

    k_deg  <<<gNnz4, T>>>(rows);
    k_scat1<<<gNnz4, T>>>(rows, cols);
    k_gath1<<<gNnz4, T>>>(rows, cols);
    k_prep <<<gNV,   T>>>();
    k_scat2<<<gNnz4, T>>>(rows, cols);
    k_gath2<<<gNnz4, T>>>(rows, cols);
    k_reduce_final<<<gNV, T>>>(x_0, W0, b0, Wl0, bl0, Wl1, bl1,
                               Wo0, bo0, Wo1, bo1, out);
}